// round 10
// baseline (speedup 1.0000x reference)
#include <cuda_runtime.h>
#include <cuda_fp16.h>

#define NN 50000
#define EE 800000
#define HID 128
#define NCLS 16
#define NGRAPH 512

#define SCAN_TPB 256
#define SCAN_NB ((NN + SCAN_TPB - 1) / SCAN_TPB)   // 196

#define GP 136   // smem pitch (halves) for both A and W tiles
#define GEMM_SMEM (2 * 128 * GP * 2)   // sA + sB bytes = 69632

// ---------------- device scratch (no allocation allowed) ----------------
__device__ __half g_tmph[NN * HID];     // fp16 dinv-scaled GEMM output
__device__ __half g_hb0 [NN * HID];
__device__ __half g_hb1 [NN * HID];
__device__ __half g_hb2 [NN * HID];
__device__ __half g_wh  [5 * HID * HID];   // fp16 weights: [0]=W_in, [1..4]=W_hid

__device__ int   g_cnt[NN];
__device__ int   g_rowptr[NN + 1];
__device__ int   g_cursor[NN];
__device__ int   g_col[EE];
__device__ float g_dinv[NN];
__device__ int   g_bsum[SCAN_NB];

__device__ float g_gsum[NGRAPH * HID];
__device__ int   g_gcnt[NGRAPH];

__device__ int   g_ei64;
__device__ int   g_b64;

__device__ __forceinline__ int load_idx(const void* p, long i, int is64) {
    return is64 ? (int)((const long long*)p)[i] : ((const int*)p)[i];
}

// ---------------- zero + dtype detection (merged) ----------------
__global__ void zero_kernel(const int* __restrict__ ei,
                            const int* __restrict__ batch) {
    int i = blockIdx.x * blockDim.x + threadIdx.x;
    if (i < NGRAPH * HID) g_gsum[i] = 0.f;
    if (i < NGRAPH) g_gcnt[i] = 0;
    if (i < NN) g_cnt[i] = 0;
    if (blockIdx.x == 0 && threadIdx.x == 0) {
        int z = 1;
        for (int k = 1; k < 257; k += 2) if (ei[k] != 0) { z = 0; break; }
        g_ei64 = z;
        z = 1;
        for (int k = 25001; k < 25257; k += 2) if (batch[k] != 0) { z = 0; break; }
        g_b64 = z;
    }
}

// ---------------- weight pre-conversion (fp32 -> fp16, once) --------------
__global__ void cvtW_kernel(const float4* __restrict__ Win,
                            const float4* __restrict__ Whid) {
    int i = blockIdx.x * blockDim.x + threadIdx.x;   // float4 index
    if (i >= 5 * 4096) return;
    float4 v = (i < 4096) ? Win[i] : Whid[i - 4096];
    __half2 h0 = __floats2half2_rn(v.x, v.y);
    __half2 h1 = __floats2half2_rn(v.z, v.w);
    ((uint2*)g_wh)[i] = make_uint2(*(unsigned*)&h0, *(unsigned*)&h1);
}

// ---------------- CSR build ----------------
__global__ void hist_kernel(const void* __restrict__ ei) {
    int is64 = g_ei64;
    int tid2 = blockIdx.x * blockDim.x + threadIdx.x;
    if (is64) {
        const longlong2* dst2 = (const longlong2*)((const long long*)ei + EE);
        for (int p = tid2; p < EE / 2; p += gridDim.x * blockDim.x) {
            longlong2 d = dst2[p];
            atomicAdd(&g_cnt[(int)d.x], 1);
            atomicAdd(&g_cnt[(int)d.y], 1);
        }
    } else {
        const int2* dst2 = (const int2*)((const int*)ei + EE);
        for (int p = tid2; p < EE / 2; p += gridDim.x * blockDim.x) {
            int2 d = dst2[p];
            atomicAdd(&g_cnt[d.x], 1);
            atomicAdd(&g_cnt[d.y], 1);
        }
    }
}

__global__ __launch_bounds__(SCAN_TPB) void scan1_kernel() {
    __shared__ int sh[SCAN_TPB];
    int tid = threadIdx.x;
    int i = blockIdx.x * SCAN_TPB + tid;
    int c = (i < NN) ? g_cnt[i] : 0;
    if (i < NN) g_dinv[i] = rsqrtf((float)(c + 1));
    sh[tid] = c;
    __syncthreads();
#pragma unroll
    for (int off = 1; off < SCAN_TPB; off <<= 1) {
        int v = (tid >= off) ? sh[tid - off] : 0;
        __syncthreads();
        sh[tid] += v;
        __syncthreads();
    }
    if (i < NN) g_rowptr[i] = sh[tid] - c;
    if (tid == SCAN_TPB - 1) g_bsum[blockIdx.x] = sh[tid];
}

__global__ __launch_bounds__(SCAN_TPB) void scan2_kernel() {
    __shared__ int sh[SCAN_TPB];
    int tid = threadIdx.x;
    int c = (tid < SCAN_NB) ? g_bsum[tid] : 0;
    sh[tid] = c;
    __syncthreads();
#pragma unroll
    for (int off = 1; off < SCAN_TPB; off <<= 1) {
        int v = (tid >= off) ? sh[tid - off] : 0;
        __syncthreads();
        sh[tid] += v;
        __syncthreads();
    }
    if (tid < SCAN_NB) g_bsum[tid] = sh[tid] - c;
}

__global__ __launch_bounds__(SCAN_TPB) void scan3_kernel() {
    int i = blockIdx.x * SCAN_TPB + threadIdx.x;
    if (i < NN) {
        int v = g_rowptr[i] + g_bsum[blockIdx.x];
        g_rowptr[i] = v;
        g_cursor[i] = v;
    }
    if (i == 0) g_rowptr[NN] = EE;
}

__global__ void fill_kernel(const void* __restrict__ ei) {
    int is64 = g_ei64;
    int tid2 = blockIdx.x * blockDim.x + threadIdx.x;
    if (is64) {
        const longlong2* src2 = (const longlong2*)ei;
        const longlong2* dst2 = (const longlong2*)((const long long*)ei + EE);
        for (int p = tid2; p < EE / 2; p += gridDim.x * blockDim.x) {
            longlong2 s = src2[p];
            longlong2 d = dst2[p];
            int pos0 = atomicAdd(&g_cursor[(int)d.x], 1);
            g_col[pos0] = (int)s.x;
            int pos1 = atomicAdd(&g_cursor[(int)d.y], 1);
            g_col[pos1] = (int)s.y;
        }
    } else {
        const int2* src2 = (const int2*)ei;
        const int2* dst2 = (const int2*)((const int*)ei + EE);
        for (int p = tid2; p < EE / 2; p += gridDim.x * blockDim.x) {
            int2 s = src2[p];
            int2 d = dst2[p];
            int pos0 = atomicAdd(&g_cursor[d.x], 1);
            g_col[pos0] = s.x;
            int pos1 = atomicAdd(&g_cursor[d.y], 1);
            g_col[pos1] = s.y;
        }
    }
}

// ---------------- tensor-core GEMM ----------------
__device__ __forceinline__ unsigned cvta_sh(const void* p) {
    return (unsigned)__cvta_generic_to_shared(p);
}
__device__ __forceinline__ void ldm_x4(unsigned* r, unsigned addr) {
    asm volatile("ldmatrix.sync.aligned.m8n8.x4.shared.b16 {%0,%1,%2,%3}, [%4];"
                 : "=r"(r[0]), "=r"(r[1]), "=r"(r[2]), "=r"(r[3]) : "r"(addr));
}
__device__ __forceinline__ void ldm_x4_t(unsigned* r, unsigned addr) {
    asm volatile("ldmatrix.sync.aligned.m8n8.x4.trans.shared.b16 {%0,%1,%2,%3}, [%4];"
                 : "=r"(r[0]), "=r"(r[1]), "=r"(r[2]), "=r"(r[3]) : "r"(addr));
}
__device__ __forceinline__ void mma16816(float* c, const unsigned* a,
                                         unsigned b0, unsigned b1) {
    asm volatile(
        "mma.sync.aligned.m16n8k16.row.col.f32.f16.f16.f32 "
        "{%0,%1,%2,%3}, {%4,%5,%6,%7}, {%8,%9}, {%0,%1,%2,%3};"
        : "+f"(c[0]), "+f"(c[1]), "+f"(c[2]), "+f"(c[3])
        : "r"(a[0]), "r"(a[1]), "r"(a[2]), "r"(a[3]), "r"(b0), "r"(b1));
}

// 256-row macro-tile per block; W staged once; two 128-row sub-tiles.
// A1f != null: load fp32 rows from A1f (input layer), else fp16 from A1 (+A2).
__global__ __launch_bounds__(256, 2) void gemm_kernel(
    const __half* __restrict__ A1, const __half* __restrict__ A2, int hasB,
    const float* __restrict__ A1f,
    const __half* __restrict__ Wh, __half* __restrict__ Ch) {
    extern __shared__ __half smem[];
    __half* sA = smem;              // 128 x GP
    __half* sB = smem + 128 * GP;   // 128 x GP

    int tid = threadIdx.x;
    int lane = tid & 31, wid = tid >> 5;
    int warpM = wid & 3, warpN = wid >> 2;

    // stage full W (128x128 fp16) once
#pragma unroll
    for (int i = 0; i < 8; i++) {
        int idx = i * 256 + tid;          // uint4 index, 2048 total
        int row = idx >> 4, c8 = idx & 15;
        uint4 w = *(const uint4*)(Wh + (long)row * 128 + c8 * 8);
        *(uint4*)&sB[row * GP + c8 * 8] = w;
    }

    for (int t = 0; t < 2; t++) {
        int rowBase = (blockIdx.x * 2 + t) * 128;

        // stage A tile: 128 rows x 128 halves
#pragma unroll
        for (int i = 0; i < 8; i++) {
            int idx = i * 256 + tid;
            int row = idx >> 4, c8 = idx & 15;
            int grow = rowBase + row;
            uint4 v = make_uint4(0, 0, 0, 0);
            if (grow < NN) {
                if (A1f) {
                    float4 f0 = *(const float4*)(A1f + (long)grow * 128 + c8 * 8);
                    float4 f1 = *(const float4*)(A1f + (long)grow * 128 + c8 * 8 + 4);
                    __half2 h0 = __floats2half2_rn(f0.x, f0.y);
                    __half2 h1 = __floats2half2_rn(f0.z, f0.w);
                    __half2 h2 = __floats2half2_rn(f1.x, f1.y);
                    __half2 h3 = __floats2half2_rn(f1.z, f1.w);
                    v = make_uint4(*(unsigned*)&h0, *(unsigned*)&h1,
                                   *(unsigned*)&h2, *(unsigned*)&h3);
                } else {
                    v = *(const uint4*)(A1 + (long)grow * 128 + c8 * 8);
                    if (hasB) {
                        uint4 u = *(const uint4*)(A2 + (long)grow * 128 + c8 * 8);
                        __half2* vh = (__half2*)&v;
                        __half2* uh = (__half2*)&u;
                        vh[0] = __hadd2(vh[0], uh[0]);
                        vh[1] = __hadd2(vh[1], uh[1]);
                        vh[2] = __hadd2(vh[2], uh[2]);
                        vh[3] = __hadd2(vh[3], uh[3]);
                    }
                }
            }
            *(uint4*)&sA[row * GP + c8 * 8] = v;
        }
        __syncthreads();

        float c[2][8][4];
#pragma unroll
        for (int mi = 0; mi < 2; mi++)
#pragma unroll
            for (int ni = 0; ni < 8; ni++)
#pragma unroll
                for (int j = 0; j < 4; j++) c[mi][ni][j] = 0.f;

#pragma unroll
        for (int kk = 0; kk < 8; kk++) {
            unsigned a[2][4];
#pragma unroll
            for (int mi = 0; mi < 2; mi++) {
                unsigned addr = cvta_sh(&sA[(warpM * 32 + mi * 16 + (lane & 15)) * GP
                                            + kk * 16 + (lane >> 4) * 8]);
                ldm_x4(a[mi], addr);
            }
            unsigned b[4][4];
#pragma unroll
            for (int nj = 0; nj < 4; nj++) {
                unsigned addr = cvta_sh(&sB[(kk * 16 + (lane & 15)) * GP
                                            + warpN * 64 + nj * 16 + (lane >> 4) * 8]);
                ldm_x4_t(b[nj], addr);
            }
#pragma unroll
            for (int mi = 0; mi < 2; mi++)
#pragma unroll
                for (int ni = 0; ni < 8; ni++) {
                    unsigned b0 = b[ni >> 1][(ni & 1) * 2];
                    unsigned b1 = b[ni >> 1][(ni & 1) * 2 + 1];
                    mma16816(c[mi][ni], a[mi], b0, b1);
                }
        }

        int gID = lane >> 2, tig = lane & 3;
#pragma unroll
        for (int mi = 0; mi < 2; mi++) {
            int r0 = rowBase + warpM * 32 + mi * 16 + gID;
            int r1 = r0 + 8;
            float d0 = (r0 < NN) ? g_dinv[r0] : 0.f;
            float d1 = (r1 < NN) ? g_dinv[r1] : 0.f;
#pragma unroll
            for (int ni = 0; ni < 8; ni++) {
                int col = warpN * 64 + ni * 8 + tig * 2;
                if (r0 < NN) {
                    __half2 h = __floats2half2_rn(d0 * c[mi][ni][0], d0 * c[mi][ni][1]);
                    *(unsigned*)(Ch + (long)r0 * 128 + col) = *(unsigned*)&h;
                }
                if (r1 < NN) {
                    __half2 h = __floats2half2_rn(d1 * c[mi][ni][2], d1 * c[mi][ni][3]);
                    *(unsigned*)(Ch + (long)r1 * 128 + col) = *(unsigned*)&h;
                }
            }
        }
        __syncthreads();   // before next sub-tile overwrites sA
    }
}

// ---------------- aggregation: half-warp (16 lanes) per node, uint4 loads --
__device__ __forceinline__ void add_h4(float* acc, uint4 v) {
    __half2* h = (__half2*)&v;
#pragma unroll
    for (int j = 0; j < 4; j++) {
        float2 f = __half22float2(h[j]);
        acc[2 * j]     += f.x;
        acc[2 * j + 1] += f.y;
    }
}

__global__ __launch_bounds__(256) void agg_kernel(
    const uint4* __restrict__ tmp, const float* __restrict__ bias,
    uint4* __restrict__ out) {
    int lane16 = threadIdx.x & 15;
    int node = (blockIdx.x * blockDim.x + threadIdx.x) >> 4;
    if (node >= NN) return;

    int beg = g_rowptr[node];
    int end = g_rowptr[node + 1];

    float acc[8] = {0.f, 0.f, 0.f, 0.f, 0.f, 0.f, 0.f, 0.f};
    int e = beg;
    for (; e + 8 <= end; e += 8) {
        uint4 v0 = tmp[(long)g_col[e    ] * 16 + lane16];
        uint4 v1 = tmp[(long)g_col[e + 1] * 16 + lane16];
        uint4 v2 = tmp[(long)g_col[e + 2] * 16 + lane16];
        uint4 v3 = tmp[(long)g_col[e + 3] * 16 + lane16];
        uint4 v4 = tmp[(long)g_col[e + 4] * 16 + lane16];
        uint4 v5 = tmp[(long)g_col[e + 5] * 16 + lane16];
        uint4 v6 = tmp[(long)g_col[e + 6] * 16 + lane16];
        uint4 v7 = tmp[(long)g_col[e + 7] * 16 + lane16];
        add_h4(acc, v0); add_h4(acc, v1); add_h4(acc, v2); add_h4(acc, v3);
        add_h4(acc, v4); add_h4(acc, v5); add_h4(acc, v6); add_h4(acc, v7);
    }
    for (; e < end; e++) add_h4(acc, tmp[(long)g_col[e] * 16 + lane16]);
    add_h4(acc, tmp[(long)node * 16 + lane16]);   // self loop

    float di = g_dinv[node];
    float4 b0 = ((const float4*)bias)[lane16 * 2];
    float4 b1 = ((const float4*)bias)[lane16 * 2 + 1];
    float o[8];
    o[0] = fmaxf(fmaf(di, acc[0], b0.x), 0.f);
    o[1] = fmaxf(fmaf(di, acc[1], b0.y), 0.f);
    o[2] = fmaxf(fmaf(di, acc[2], b0.z), 0.f);
    o[3] = fmaxf(fmaf(di, acc[3], b0.w), 0.f);
    o[4] = fmaxf(fmaf(di, acc[4], b1.x), 0.f);
    o[5] = fmaxf(fmaf(di, acc[5], b1.y), 0.f);
    o[6] = fmaxf(fmaf(di, acc[6], b1.z), 0.f);
    o[7] = fmaxf(fmaf(di, acc[7], b1.w), 0.f);
    __half2 h[4];
    h[0] = __floats2half2_rn(o[0], o[1]);
    h[1] = __floats2half2_rn(o[2], o[3]);
    h[2] = __floats2half2_rn(o[4], o[5]);
    h[3] = __floats2half2_rn(o[6], o[7]);
    out[(long)node * 16 + lane16] = *(uint4*)h;
}

// ---------------- pooling over sorted batch ids ----------------
#define POOL_NODES 64
__global__ void pool_kernel(const __half* __restrict__ cur,
                            const void* __restrict__ batch) {
    int is64 = g_b64;
    int f = threadIdx.x;
    int start = blockIdx.x * POOL_NODES;
    if (start >= NN) return;
    int endn = start + POOL_NODES;
    if (endn > NN) endn = NN;

    int curg = load_idx(batch, start, is64);
    float acc = 0.f;
    int cnt = 0;
    for (int nd = start; nd < endn; nd++) {
        int gg = load_idx(batch, nd, is64);
        if (gg != curg) {
            atomicAdd(&g_gsum[curg * HID + f], acc);
            if (f == 0) atomicAdd(&g_gcnt[curg], cnt);
            acc = 0.f; cnt = 0; curg = gg;
        }
        acc += __half2float(cur[(long)nd * HID + f]);
        cnt++;
    }
    atomicAdd(&g_gsum[curg * HID + f], acc);
    if (f == 0) atomicAdd(&g_gcnt[curg], cnt);
}

// ---------------- mean + linear head + outputs ----------------
__global__ void final_kernel(const float* __restrict__ Wl,
                             const float* __restrict__ bl,
                             float* __restrict__ out) {
    __shared__ float sm[HID];
    int g = blockIdx.x;
    int f = threadIdx.x;
    float c = (float)g_gcnt[g];
    c = fmaxf(c, 1.f);
    float m = g_gsum[g * HID + f] / c;
    sm[f] = m;
    out[NGRAPH * NCLS + (long)g * HID + f] = m;
    __syncthreads();
    if (f < NCLS) {
        float y = bl[f];
#pragma unroll 8
        for (int k = 0; k < HID; k++) y = fmaf(sm[k], Wl[k * NCLS + f], y);
        out[g * NCLS + f] = y;
    }
}

// ---------------- host ----------------
extern "C" void kernel_launch(void* const* d_in, const int* in_sizes, int n_in,
                              void* d_out, int out_size) {
    const float* x     = (const float*)d_in[0];
    const void*  ei    = d_in[1];
    const void*  batch = d_in[2];
    const float* W_in  = (const float*)d_in[3];
    const float* b_in  = (const float*)d_in[4];
    const float* W_hid = (const float*)d_in[5];
    const float* b_hid = (const float*)d_in[6];
    const float* W_lin = (const float*)d_in[7];
    const float* b_lin = (const float*)d_in[8];
    float* out = (float*)d_out;

    __half *tmph, *hb0, *hb1, *hb2, *wh;
    cudaGetSymbolAddress((void**)&tmph, g_tmph);
    cudaGetSymbolAddress((void**)&hb0, g_hb0);
    cudaGetSymbolAddress((void**)&hb1, g_hb1);
    cudaGetSymbolAddress((void**)&hb2, g_hb2);
    cudaGetSymbolAddress((void**)&wh,  g_wh);

    cudaFuncSetAttribute(gemm_kernel,
                         cudaFuncAttributeMaxDynamicSharedMemorySize, GEMM_SMEM);

    zero_kernel<<<(NGRAPH * HID + 255) / 256, 256>>>((const int*)ei,
                                                     (const int*)batch);
    cvtW_kernel<<<(5 * 4096 + 255) / 256, 256>>>((const float4*)W_in,
                                                 (const float4*)W_hid);
    hist_kernel<<<1024, 256>>>(ei);
    scan1_kernel<<<SCAN_NB, SCAN_TPB>>>();
    scan2_kernel<<<1, SCAN_TPB>>>();
    scan3_kernel<<<SCAN_NB, SCAN_TPB>>>();
    fill_kernel<<<1024, 256>>>(ei);

    const int GEMM_GRID = (NN + 255) / 256;   // 196 blocks, 256 rows each
    const int AGG_GRID  = (NN * 16 + 255) / 256;

    // input layer: fp32 x read directly
    gemm_kernel<<<GEMM_GRID, 256, GEMM_SMEM>>>(nullptr, nullptr, 0, x,
                                               wh + 0 * 16384, tmph);
    agg_kernel<<<AGG_GRID, 256>>>((const uint4*)tmph, b_in, (uint4*)hb0);
    // layer 0
    gemm_kernel<<<GEMM_GRID, 256, GEMM_SMEM>>>(hb0, hb0, 0, nullptr,
                                               wh + 1 * 16384, tmph);
    agg_kernel<<<AGG_GRID, 256>>>((const uint4*)tmph, b_hid + 0 * HID, (uint4*)hb1);
    // layer 1
    gemm_kernel<<<GEMM_GRID, 256, GEMM_SMEM>>>(hb1, hb0, 1, nullptr,
                                               wh + 2 * 16384, tmph);
    agg_kernel<<<AGG_GRID, 256>>>((const uint4*)tmph, b_hid + 1 * HID, (uint4*)hb2);
    // layer 2
    gemm_kernel<<<GEMM_GRID, 256, GEMM_SMEM>>>(hb2, hb1, 1, nullptr,
                                               wh + 3 * 16384, tmph);
    agg_kernel<<<AGG_GRID, 256>>>((const uint4*)tmph, b_hid + 2 * HID, (uint4*)hb0);
    // layer 3
    gemm_kernel<<<GEMM_GRID, 256, GEMM_SMEM>>>(hb0, hb2, 1, nullptr,
                                               wh + 4 * 16384, tmph);
    agg_kernel<<<AGG_GRID, 256>>>((const uint4*)tmph, b_hid + 3 * HID, (uint4*)hb1);

    pool_kernel<<<(NN + POOL_NODES - 1) / POOL_NODES, 128>>>(hb1, batch);
    final_kernel<<<NGRAPH, HID>>>(W_lin, b_lin, out);
}

// round 11
// speedup vs baseline: 1.0904x; 1.0904x over previous
#include <cuda_runtime.h>
#include <cuda_fp16.h>

#define NN 50000
#define EE 800000
#define HID 128
#define NCLS 16
#define NGRAPH 512

#define SCAN_TPB 256
#define SCAN_NB ((NN + SCAN_TPB - 1) / SCAN_TPB)   // 196

// ---------------- device scratch (no allocation allowed) ----------------
__device__ __half g_tmph[NN * HID];     // fp16 dinv-scaled GEMM output
__device__ __half g_hb0 [NN * HID];
__device__ __half g_hb1 [NN * HID];
__device__ __half g_hb2 [NN * HID];
__device__ __half g_wh  [5 * HID * HID];   // fp16 weights: [0]=W_in, [1..4]=W_hid

__device__ int   g_cnt[NN];
__device__ int   g_rowptr[NN + 1];
__device__ int   g_cursor[NN];
__device__ int   g_col[EE];
__device__ float g_dinv[NN];
__device__ int   g_bsum[SCAN_NB];

__device__ float g_gsum[NGRAPH * HID];
__device__ int   g_gcnt[NGRAPH];

__device__ int   g_ei64;
__device__ int   g_b64;

__device__ __forceinline__ int load_idx(const void* p, long i, int is64) {
    return is64 ? (int)((const long long*)p)[i] : ((const int*)p)[i];
}

// ---------------- zero + dtype detection (merged) ----------------
__global__ void zero_kernel(const int* __restrict__ ei,
                            const int* __restrict__ batch) {
    int i = blockIdx.x * blockDim.x + threadIdx.x;
    if (i < NGRAPH * HID) g_gsum[i] = 0.f;
    if (i < NGRAPH) g_gcnt[i] = 0;
    if (i < NN) g_cnt[i] = 0;
    if (blockIdx.x == 0 && threadIdx.x == 0) {
        int z = 1;
        for (int k = 1; k < 257; k += 2) if (ei[k] != 0) { z = 0; break; }
        g_ei64 = z;
        z = 1;
        for (int k = 25001; k < 25257; k += 2) if (batch[k] != 0) { z = 0; break; }
        g_b64 = z;
    }
}

// ---------------- weight pre-conversion (fp32 -> fp16, once) --------------
__global__ void cvtW_kernel(const float4* __restrict__ Win,
                            const float4* __restrict__ Whid) {
    int i = blockIdx.x * blockDim.x + threadIdx.x;   // float4 index
    if (i >= 5 * 4096) return;
    float4 v = (i < 4096) ? Win[i] : Whid[i - 4096];
    __half2 h0 = __floats2half2_rn(v.x, v.y);
    __half2 h1 = __floats2half2_rn(v.z, v.w);
    ((uint2*)g_wh)[i] = make_uint2(*(unsigned*)&h0, *(unsigned*)&h1);
}

// ---------------- CSR build ----------------
__global__ void hist_kernel(const void* __restrict__ ei) {
    int is64 = g_ei64;
    int tid2 = blockIdx.x * blockDim.x + threadIdx.x;
    if (is64) {
        const longlong2* dst2 = (const longlong2*)((const long long*)ei + EE);
        for (int p = tid2; p < EE / 2; p += gridDim.x * blockDim.x) {
            longlong2 d = dst2[p];
            atomicAdd(&g_cnt[(int)d.x], 1);
            atomicAdd(&g_cnt[(int)d.y], 1);
        }
    } else {
        const int2* dst2 = (const int2*)((const int*)ei + EE);
        for (int p = tid2; p < EE / 2; p += gridDim.x * blockDim.x) {
            int2 d = dst2[p];
            atomicAdd(&g_cnt[d.x], 1);
            atomicAdd(&g_cnt[d.y], 1);
        }
    }
}

__global__ __launch_bounds__(SCAN_TPB) void scan1_kernel() {
    __shared__ int sh[SCAN_TPB];
    int tid = threadIdx.x;
    int i = blockIdx.x * SCAN_TPB + tid;
    int c = (i < NN) ? g_cnt[i] : 0;
    if (i < NN) g_dinv[i] = rsqrtf((float)(c + 1));
    sh[tid] = c;
    __syncthreads();
#pragma unroll
    for (int off = 1; off < SCAN_TPB; off <<= 1) {
        int v = (tid >= off) ? sh[tid - off] : 0;
        __syncthreads();
        sh[tid] += v;
        __syncthreads();
    }
    if (i < NN) g_rowptr[i] = sh[tid] - c;
    if (tid == SCAN_TPB - 1) g_bsum[blockIdx.x] = sh[tid];
}

__global__ __launch_bounds__(SCAN_TPB) void scan2_kernel() {
    __shared__ int sh[SCAN_TPB];
    int tid = threadIdx.x;
    int c = (tid < SCAN_NB) ? g_bsum[tid] : 0;
    sh[tid] = c;
    __syncthreads();
#pragma unroll
    for (int off = 1; off < SCAN_TPB; off <<= 1) {
        int v = (tid >= off) ? sh[tid - off] : 0;
        __syncthreads();
        sh[tid] += v;
        __syncthreads();
    }
    if (tid < SCAN_NB) g_bsum[tid] = sh[tid] - c;
}

__global__ __launch_bounds__(SCAN_TPB) void scan3_kernel() {
    int i = blockIdx.x * SCAN_TPB + threadIdx.x;
    if (i < NN) {
        int v = g_rowptr[i] + g_bsum[blockIdx.x];
        g_rowptr[i] = v;
        g_cursor[i] = v;
    }
    if (i == 0) g_rowptr[NN] = EE;
}

__global__ void fill_kernel(const void* __restrict__ ei) {
    int is64 = g_ei64;
    int tid2 = blockIdx.x * blockDim.x + threadIdx.x;
    if (is64) {
        const longlong2* src2 = (const longlong2*)ei;
        const longlong2* dst2 = (const longlong2*)((const long long*)ei + EE);
        for (int p = tid2; p < EE / 2; p += gridDim.x * blockDim.x) {
            longlong2 s = src2[p];
            longlong2 d = dst2[p];
            int pos0 = atomicAdd(&g_cursor[(int)d.x], 1);
            g_col[pos0] = (int)s.x;
            int pos1 = atomicAdd(&g_cursor[(int)d.y], 1);
            g_col[pos1] = (int)s.y;
        }
    } else {
        const int2* src2 = (const int2*)ei;
        const int2* dst2 = (const int2*)((const int*)ei + EE);
        for (int p = tid2; p < EE / 2; p += gridDim.x * blockDim.x) {
            int2 s = src2[p];
            int2 d = dst2[p];
            int pos0 = atomicAdd(&g_cursor[d.x], 1);
            g_col[pos0] = s.x;
            int pos1 = atomicAdd(&g_cursor[d.y], 1);
            g_col[pos1] = s.y;
        }
    }
}

// ---------------- tensor-core GEMM ----------------
#define GP 72    // sA pitch (halves)
#define BP 136   // sB pitch (halves)

__device__ __forceinline__ unsigned cvta_sh(const void* p) {
    return (unsigned)__cvta_generic_to_shared(p);
}
__device__ __forceinline__ void ldm_x4(unsigned* r, unsigned addr) {
    asm volatile("ldmatrix.sync.aligned.m8n8.x4.shared.b16 {%0,%1,%2,%3}, [%4];"
                 : "=r"(r[0]), "=r"(r[1]), "=r"(r[2]), "=r"(r[3]) : "r"(addr));
}
__device__ __forceinline__ void ldm_x4_t(unsigned* r, unsigned addr) {
    asm volatile("ldmatrix.sync.aligned.m8n8.x4.trans.shared.b16 {%0,%1,%2,%3}, [%4];"
                 : "=r"(r[0]), "=r"(r[1]), "=r"(r[2]), "=r"(r[3]) : "r"(addr));
}
__device__ __forceinline__ void mma16816(float* c, const unsigned* a,
                                         unsigned b0, unsigned b1) {
    asm volatile(
        "mma.sync.aligned.m16n8k16.row.col.f32.f16.f16.f32 "
        "{%0,%1,%2,%3}, {%4,%5,%6,%7}, {%8,%9}, {%0,%1,%2,%3};"
        : "+f"(c[0]), "+f"(c[1]), "+f"(c[2]), "+f"(c[3])
        : "r"(a[0]), "r"(a[1]), "r"(a[2]), "r"(a[3]), "r"(b0), "r"(b1));
}

// A1f != null: load fp32 rows from A1f (input layer), else fp16 from A1 (+A2).
__global__ __launch_bounds__(256, 2) void gemm_kernel(
    const __half* __restrict__ A1, const __half* __restrict__ A2, int hasB,
    const float* __restrict__ A1f,
    const __half* __restrict__ Wh, __half* __restrict__ Ch) {
    __shared__ __half sA[128 * GP];
    __shared__ __half sB[64 * BP];

    int tid = threadIdx.x;
    int lane = tid & 31, wid = tid >> 5;
    int warpM = wid & 3, warpN = wid >> 2;
    int rowBase = blockIdx.x * 128;

    float c[2][8][4];
#pragma unroll
    for (int mi = 0; mi < 2; mi++)
#pragma unroll
        for (int ni = 0; ni < 8; ni++)
#pragma unroll
            for (int j = 0; j < 4; j++) c[mi][ni][j] = 0.f;

    for (int k0 = 0; k0 < 128; k0 += 64) {
        // stage A chunk: 128 rows x 64 halves
#pragma unroll
        for (int i = 0; i < 4; i++) {
            int idx = i * 256 + tid;
            int row = idx >> 3, c8 = idx & 7;
            int grow = rowBase + row;
            uint4 v = make_uint4(0, 0, 0, 0);
            if (grow < NN) {
                if (A1f) {
                    float4 f0 = *(const float4*)(A1f + (long)grow * 128 + k0 + c8 * 8);
                    float4 f1 = *(const float4*)(A1f + (long)grow * 128 + k0 + c8 * 8 + 4);
                    __half2 h0 = __floats2half2_rn(f0.x, f0.y);
                    __half2 h1 = __floats2half2_rn(f0.z, f0.w);
                    __half2 h2 = __floats2half2_rn(f1.x, f1.y);
                    __half2 h3 = __floats2half2_rn(f1.z, f1.w);
                    v = make_uint4(*(unsigned*)&h0, *(unsigned*)&h1,
                                   *(unsigned*)&h2, *(unsigned*)&h3);
                } else {
                    v = *(const uint4*)(A1 + (long)grow * 128 + k0 + c8 * 8);
                    if (hasB) {
                        uint4 u = *(const uint4*)(A2 + (long)grow * 128 + k0 + c8 * 8);
                        __half2* vh = (__half2*)&v;
                        __half2* uh = (__half2*)&u;
                        vh[0] = __hadd2(vh[0], uh[0]);
                        vh[1] = __hadd2(vh[1], uh[1]);
                        vh[2] = __hadd2(vh[2], uh[2]);
                        vh[3] = __hadd2(vh[3], uh[3]);
                    }
                }
            }
            *(uint4*)&sA[row * GP + c8 * 8] = v;
        }
        // stage W chunk: 64 k-rows x 128 cols fp16 (uint4 loads)
#pragma unroll
        for (int i = 0; i < 4; i++) {
            int idx = i * 256 + tid;          // uint4 index, 1024 total
            int row = idx >> 4, c8 = idx & 15;
            uint4 w = *(const uint4*)(Wh + (long)(k0 + row) * 128 + c8 * 8);
            *(uint4*)&sB[row * BP + c8 * 8] = w;
        }
        __syncthreads();

#pragma unroll
        for (int kk = 0; kk < 4; kk++) {
            unsigned a[2][4];
#pragma unroll
            for (int mi = 0; mi < 2; mi++) {
                unsigned addr = cvta_sh(&sA[(warpM * 32 + mi * 16 + (lane & 15)) * GP
                                            + kk * 16 + (lane >> 4) * 8]);
                ldm_x4(a[mi], addr);
            }
            unsigned b[4][4];
#pragma unroll
            for (int nj = 0; nj < 4; nj++) {
                unsigned addr = cvta_sh(&sB[(kk * 16 + (lane & 15)) * BP
                                            + warpN * 64 + nj * 16 + (lane >> 4) * 8]);
                ldm_x4_t(b[nj], addr);
            }
#pragma unroll
            for (int mi = 0; mi < 2; mi++)
#pragma unroll
                for (int ni = 0; ni < 8; ni++) {
                    unsigned b0 = b[ni >> 1][(ni & 1) * 2];
                    unsigned b1 = b[ni >> 1][(ni & 1) * 2 + 1];
                    mma16816(c[mi][ni], a[mi], b0, b1);
                }
        }
        __syncthreads();
    }

    int gID = lane >> 2, tig = lane & 3;
#pragma unroll
    for (int mi = 0; mi < 2; mi++) {
        int r0 = rowBase + warpM * 32 + mi * 16 + gID;
        int r1 = r0 + 8;
        float d0 = (r0 < NN) ? g_dinv[r0] : 0.f;
        float d1 = (r1 < NN) ? g_dinv[r1] : 0.f;
#pragma unroll
        for (int ni = 0; ni < 8; ni++) {
            int col = warpN * 64 + ni * 8 + tig * 2;
            if (r0 < NN) {
                __half2 h = __floats2half2_rn(d0 * c[mi][ni][0], d0 * c[mi][ni][1]);
                *(unsigned*)(Ch + (long)r0 * 128 + col) = *(unsigned*)&h;
            }
            if (r1 < NN) {
                __half2 h = __floats2half2_rn(d1 * c[mi][ni][2], d1 * c[mi][ni][3]);
                *(unsigned*)(Ch + (long)r1 * 128 + col) = *(unsigned*)&h;
            }
        }
    }
}

// ---------------- aggregation: half-warp (16 lanes) per node, uint4 loads --
__device__ __forceinline__ void add_h4(float* acc, uint4 v) {
    __half2* h = (__half2*)&v;
#pragma unroll
    for (int j = 0; j < 4; j++) {
        float2 f = __half22float2(h[j]);
        acc[2 * j]     += f.x;
        acc[2 * j + 1] += f.y;
    }
}

__global__ __launch_bounds__(256) void agg_kernel(
    const uint4* __restrict__ tmp, const float* __restrict__ bias,
    uint4* __restrict__ out) {
    int lane16 = threadIdx.x & 15;
    int node = (blockIdx.x * blockDim.x + threadIdx.x) >> 4;
    if (node >= NN) return;

    int beg = g_rowptr[node];
    int end = g_rowptr[node + 1];

    float acc[8] = {0.f, 0.f, 0.f, 0.f, 0.f, 0.f, 0.f, 0.f};
    int e = beg;
    for (; e + 8 <= end; e += 8) {
        uint4 v0 = tmp[(long)g_col[e    ] * 16 + lane16];
        uint4 v1 = tmp[(long)g_col[e + 1] * 16 + lane16];
        uint4 v2 = tmp[(long)g_col[e + 2] * 16 + lane16];
        uint4 v3 = tmp[(long)g_col[e + 3] * 16 + lane16];
        uint4 v4 = tmp[(long)g_col[e + 4] * 16 + lane16];
        uint4 v5 = tmp[(long)g_col[e + 5] * 16 + lane16];
        uint4 v6 = tmp[(long)g_col[e + 6] * 16 + lane16];
        uint4 v7 = tmp[(long)g_col[e + 7] * 16 + lane16];
        add_h4(acc, v0); add_h4(acc, v1); add_h4(acc, v2); add_h4(acc, v3);
        add_h4(acc, v4); add_h4(acc, v5); add_h4(acc, v6); add_h4(acc, v7);
    }
    for (; e < end; e++) add_h4(acc, tmp[(long)g_col[e] * 16 + lane16]);
    add_h4(acc, tmp[(long)node * 16 + lane16]);   // self loop

    float di = g_dinv[node];
    float4 b0 = ((const float4*)bias)[lane16 * 2];
    float4 b1 = ((const float4*)bias)[lane16 * 2 + 1];
    float o[8];
    o[0] = fmaxf(fmaf(di, acc[0], b0.x), 0.f);
    o[1] = fmaxf(fmaf(di, acc[1], b0.y), 0.f);
    o[2] = fmaxf(fmaf(di, acc[2], b0.z), 0.f);
    o[3] = fmaxf(fmaf(di, acc[3], b0.w), 0.f);
    o[4] = fmaxf(fmaf(di, acc[4], b1.x), 0.f);
    o[5] = fmaxf(fmaf(di, acc[5], b1.y), 0.f);
    o[6] = fmaxf(fmaf(di, acc[6], b1.z), 0.f);
    o[7] = fmaxf(fmaf(di, acc[7], b1.w), 0.f);
    __half2 h[4];
    h[0] = __floats2half2_rn(o[0], o[1]);
    h[1] = __floats2half2_rn(o[2], o[3]);
    h[2] = __floats2half2_rn(o[4], o[5]);
    h[3] = __floats2half2_rn(o[6], o[7]);
    out[(long)node * 16 + lane16] = *(uint4*)h;
}

// ---------------- pooling over sorted batch ids ----------------
#define POOL_NODES 64
__global__ void pool_kernel(const __half* __restrict__ cur,
                            const void* __restrict__ batch) {
    int is64 = g_b64;
    int f = threadIdx.x;
    int start = blockIdx.x * POOL_NODES;
    if (start >= NN) return;
    int endn = start + POOL_NODES;
    if (endn > NN) endn = NN;

    int curg = load_idx(batch, start, is64);
    float acc = 0.f;
    int cnt = 0;
    for (int nd = start; nd < endn; nd++) {
        int gg = load_idx(batch, nd, is64);
        if (gg != curg) {
            atomicAdd(&g_gsum[curg * HID + f], acc);
            if (f == 0) atomicAdd(&g_gcnt[curg], cnt);
            acc = 0.f; cnt = 0; curg = gg;
        }
        acc += __half2float(cur[(long)nd * HID + f]);
        cnt++;
    }
    atomicAdd(&g_gsum[curg * HID + f], acc);
    if (f == 0) atomicAdd(&g_gcnt[curg], cnt);
}

// ---------------- mean + linear head + outputs ----------------
__global__ void final_kernel(const float* __restrict__ Wl,
                             const float* __restrict__ bl,
                             float* __restrict__ out) {
    __shared__ float sm[HID];
    int g = blockIdx.x;
    int f = threadIdx.x;
    float c = (float)g_gcnt[g];
    c = fmaxf(c, 1.f);
    float m = g_gsum[g * HID + f] / c;
    sm[f] = m;
    out[NGRAPH * NCLS + (long)g * HID + f] = m;
    __syncthreads();
    if (f < NCLS) {
        float y = bl[f];
#pragma unroll 8
        for (int k = 0; k < HID; k++) y = fmaf(sm[k], Wl[k * NCLS + f], y);
        out[g * NCLS + f] = y;
    }
}

// ---------------- host ----------------
extern "C" void kernel_launch(void* const* d_in, const int* in_sizes, int n_in,
                              void* d_out, int out_size) {
    const float* x     = (const float*)d_in[0];
    const void*  ei    = d_in[1];
    const void*  batch = d_in[2];
    const float* W_in  = (const float*)d_in[3];
    const float* b_in  = (const float*)d_in[4];
    const float* W_hid = (const float*)d_in[5];
    const float* b_hid = (const float*)d_in[6];
    const float* W_lin = (const float*)d_in[7];
    const float* b_lin = (const float*)d_in[8];
    float* out = (float*)d_out;

    __half *tmph, *hb0, *hb1, *hb2, *wh;
    cudaGetSymbolAddress((void**)&tmph, g_tmph);
    cudaGetSymbolAddress((void**)&hb0, g_hb0);
    cudaGetSymbolAddress((void**)&hb1, g_hb1);
    cudaGetSymbolAddress((void**)&hb2, g_hb2);
    cudaGetSymbolAddress((void**)&wh,  g_wh);

    zero_kernel<<<(NGRAPH * HID + 255) / 256, 256>>>((const int*)ei,
                                                     (const int*)batch);
    cvtW_kernel<<<(5 * 4096 + 255) / 256, 256>>>((const float4*)W_in,
                                                 (const float4*)W_hid);
    hist_kernel<<<1024, 256>>>(ei);
    scan1_kernel<<<SCAN_NB, SCAN_TPB>>>();
    scan2_kernel<<<1, SCAN_TPB>>>();
    scan3_kernel<<<SCAN_NB, SCAN_TPB>>>();
    fill_kernel<<<1024, 256>>>(ei);

    const int GEMM_GRID = (NN + 127) / 128;
    const int AGG_GRID  = (NN * 16 + 255) / 256;

    // input layer: fp32 x read directly
    gemm_kernel<<<GEMM_GRID, 256>>>(nullptr, nullptr, 0, x, wh + 0 * 16384, tmph);
    agg_kernel<<<AGG_GRID, 256>>>((const uint4*)tmph, b_in, (uint4*)hb0);
    // layer 0
    gemm_kernel<<<GEMM_GRID, 256>>>(hb0, hb0, 0, nullptr, wh + 1 * 16384, tmph);
    agg_kernel<<<AGG_GRID, 256>>>((const uint4*)tmph, b_hid + 0 * HID, (uint4*)hb1);
    // layer 1
    gemm_kernel<<<GEMM_GRID, 256>>>(hb1, hb0, 1, nullptr, wh + 2 * 16384, tmph);
    agg_kernel<<<AGG_GRID, 256>>>((const uint4*)tmph, b_hid + 1 * HID, (uint4*)hb2);
    // layer 2
    gemm_kernel<<<GEMM_GRID, 256>>>(hb2, hb1, 1, nullptr, wh + 3 * 16384, tmph);
    agg_kernel<<<AGG_GRID, 256>>>((const uint4*)tmph, b_hid + 2 * HID, (uint4*)hb0);
    // layer 3
    gemm_kernel<<<GEMM_GRID, 256>>>(hb0, hb2, 1, nullptr, wh + 4 * 16384, tmph);
    agg_kernel<<<AGG_GRID, 256>>>((const uint4*)tmph, b_hid + 3 * HID, (uint4*)hb1);

    pool_kernel<<<(NN + POOL_NODES - 1) / POOL_NODES, 128>>>(hb1, batch);
    final_kernel<<<NGRAPH, HID>>>(W_lin, b_lin, out);
}

// round 12
// speedup vs baseline: 1.0995x; 1.0084x over previous
#include <cuda_runtime.h>
#include <cuda_fp16.h>

#define NN 50000
#define EE 800000
#define HID 128
#define NCLS 16
#define NGRAPH 512

#define SCAN_TPB 256
#define SCAN_NB ((NN + SCAN_TPB - 1) / SCAN_TPB)   // 196

// ---------------- device scratch (no allocation allowed) ----------------
__device__ __half g_tmph[NN * HID];
__device__ __half g_hb0 [NN * HID];
__device__ __half g_hb1 [NN * HID];
__device__ __half g_hb2 [NN * HID];
__device__ __half g_wh  [5 * HID * HID];

__device__ int   g_cnt[NN];
__device__ int   g_rowptr[NN + 1];
__device__ int   g_cursor[NN];
__device__ int   g_col[EE];
__device__ float g_dinv[NN];
__device__ int   g_bsum[SCAN_NB];

__device__ float g_gsum[NGRAPH * HID];
__device__ int   g_gcnt[NGRAPH];

__device__ int   g_ei64;
__device__ int   g_b64;

__device__ __forceinline__ int load_idx(const void* p, long i, int is64) {
    return is64 ? (int)((const long long*)p)[i] : ((const int*)p)[i];
}

// ---------------- zero + dtype detection (merged) ----------------
__global__ void zero_kernel(const int* __restrict__ ei,
                            const int* __restrict__ batch) {
    int i = blockIdx.x * blockDim.x + threadIdx.x;
    if (i < NGRAPH * HID) g_gsum[i] = 0.f;
    if (i < NGRAPH) g_gcnt[i] = 0;
    if (i < NN) g_cnt[i] = 0;
    if (blockIdx.x == 0 && threadIdx.x == 0) {
        int z = 1;
        for (int k = 1; k < 257; k += 2) if (ei[k] != 0) { z = 0; break; }
        g_ei64 = z;
        z = 1;
        for (int k = 25001; k < 25257; k += 2) if (batch[k] != 0) { z = 0; break; }
        g_b64 = z;
    }
}

// ---------------- weight pre-conversion (fp32 -> fp16, once) --------------
__global__ void cvtW_kernel(const float4* __restrict__ Win,
                            const float4* __restrict__ Whid) {
    int i = blockIdx.x * blockDim.x + threadIdx.x;
    if (i >= 5 * 4096) return;
    float4 v = (i < 4096) ? Win[i] : Whid[i - 4096];
    __half2 h0 = __floats2half2_rn(v.x, v.y);
    __half2 h1 = __floats2half2_rn(v.z, v.w);
    ((uint2*)g_wh)[i] = make_uint2(*(unsigned*)&h0, *(unsigned*)&h1);
}

// ---------------- CSR build ----------------
__global__ void hist_kernel(const void* __restrict__ ei) {
    int is64 = g_ei64;
    int tid2 = blockIdx.x * blockDim.x + threadIdx.x;
    if (is64) {
        const longlong2* dst2 = (const longlong2*)((const long long*)ei + EE);
        for (int p = tid2; p < EE / 2; p += gridDim.x * blockDim.x) {
            longlong2 d = dst2[p];
            atomicAdd(&g_cnt[(int)d.x], 1);
            atomicAdd(&g_cnt[(int)d.y], 1);
        }
    } else {
        const int2* dst2 = (const int2*)((const int*)ei + EE);
        for (int p = tid2; p < EE / 2; p += gridDim.x * blockDim.x) {
            int2 d = dst2[p];
            atomicAdd(&g_cnt[d.x], 1);
            atomicAdd(&g_cnt[d.y], 1);
        }
    }
}

__global__ __launch_bounds__(SCAN_TPB) void scan1_kernel() {
    __shared__ int sh[SCAN_TPB];
    int tid = threadIdx.x;
    int i = blockIdx.x * SCAN_TPB + tid;
    int c = (i < NN) ? g_cnt[i] : 0;
    if (i < NN) g_dinv[i] = rsqrtf((float)(c + 1));
    sh[tid] = c;
    __syncthreads();
#pragma unroll
    for (int off = 1; off < SCAN_TPB; off <<= 1) {
        int v = (tid >= off) ? sh[tid - off] : 0;
        __syncthreads();
        sh[tid] += v;
        __syncthreads();
    }
    if (i < NN) g_rowptr[i] = sh[tid] - c;
    if (tid == SCAN_TPB - 1) g_bsum[blockIdx.x] = sh[tid];
}

// merged scan2+scan3: each block reduces block-sums of lower blocks itself
__global__ __launch_bounds__(SCAN_TPB) void scan23_kernel() {
    __shared__ int sh[SCAN_TPB];
    int tid = threadIdx.x;
    sh[tid] = (tid < (int)blockIdx.x && tid < SCAN_NB) ? g_bsum[tid] : 0;
    __syncthreads();
#pragma unroll
    for (int off = SCAN_TPB / 2; off > 0; off >>= 1) {
        if (tid < off) sh[tid] += sh[tid + off];
        __syncthreads();
    }
    int offset = sh[0];
    int i = blockIdx.x * SCAN_TPB + tid;
    if (i < NN) {
        int v = g_rowptr[i] + offset;
        g_rowptr[i] = v;
        g_cursor[i] = v;
    }
    if (i == 0) g_rowptr[NN] = EE;
}

__global__ void fill_kernel(const void* __restrict__ ei) {
    int is64 = g_ei64;
    int tid2 = blockIdx.x * blockDim.x + threadIdx.x;
    if (is64) {
        const longlong2* src2 = (const longlong2*)ei;
        const longlong2* dst2 = (const longlong2*)((const long long*)ei + EE);
        for (int p = tid2; p < EE / 2; p += gridDim.x * blockDim.x) {
            longlong2 s = src2[p];
            longlong2 d = dst2[p];
            int pos0 = atomicAdd(&g_cursor[(int)d.x], 1);
            g_col[pos0] = (int)s.x;
            int pos1 = atomicAdd(&g_cursor[(int)d.y], 1);
            g_col[pos1] = (int)s.y;
        }
    } else {
        const int2* src2 = (const int2*)ei;
        const int2* dst2 = (const int2*)((const int*)ei + EE);
        for (int p = tid2; p < EE / 2; p += gridDim.x * blockDim.x) {
            int2 s = src2[p];
            int2 d = dst2[p];
            int pos0 = atomicAdd(&g_cursor[d.x], 1);
            g_col[pos0] = s.x;
            int pos1 = atomicAdd(&g_cursor[d.y], 1);
            g_col[pos1] = s.y;
        }
    }
}

// ---------------- tensor-core GEMM ----------------
#define GP 72    // sA pitch (halves)
#define BP 136   // sB pitch (halves)

__device__ __forceinline__ unsigned cvta_sh(const void* p) {
    return (unsigned)__cvta_generic_to_shared(p);
}
__device__ __forceinline__ void ldm_x4(unsigned* r, unsigned addr) {
    asm volatile("ldmatrix.sync.aligned.m8n8.x4.shared.b16 {%0,%1,%2,%3}, [%4];"
                 : "=r"(r[0]), "=r"(r[1]), "=r"(r[2]), "=r"(r[3]) : "r"(addr));
}
__device__ __forceinline__ void ldm_x4_t(unsigned* r, unsigned addr) {
    asm volatile("ldmatrix.sync.aligned.m8n8.x4.trans.shared.b16 {%0,%1,%2,%3}, [%4];"
                 : "=r"(r[0]), "=r"(r[1]), "=r"(r[2]), "=r"(r[3]) : "r"(addr));
}
__device__ __forceinline__ void mma16816(float* c, const unsigned* a,
                                         unsigned b0, unsigned b1) {
    asm volatile(
        "mma.sync.aligned.m16n8k16.row.col.f32.f16.f16.f32 "
        "{%0,%1,%2,%3}, {%4,%5,%6,%7}, {%8,%9}, {%0,%1,%2,%3};"
        : "+f"(c[0]), "+f"(c[1]), "+f"(c[2]), "+f"(c[3])
        : "r"(a[0]), "r"(a[1]), "r"(a[2]), "r"(a[3]), "r"(b0), "r"(b1));
}

// A1f != null: fp32 rows from A1f; scaleOut: multiply rows by dinv[row].
__global__ __launch_bounds__(256, 2) void gemm_kernel(
    const __half* __restrict__ A1, const __half* __restrict__ A2, int hasB,
    const float* __restrict__ A1f, int scaleOut,
    const __half* __restrict__ Wh, __half* __restrict__ Ch) {
    __shared__ __half sA[128 * GP];
    __shared__ __half sB[64 * BP];

    int tid = threadIdx.x;
    int lane = tid & 31, wid = tid >> 5;
    int warpM = wid & 3, warpN = wid >> 2;
    int rowBase = blockIdx.x * 128;

    float c[2][8][4];
#pragma unroll
    for (int mi = 0; mi < 2; mi++)
#pragma unroll
        for (int ni = 0; ni < 8; ni++)
#pragma unroll
            for (int j = 0; j < 4; j++) c[mi][ni][j] = 0.f;

    for (int k0 = 0; k0 < 128; k0 += 64) {
#pragma unroll
        for (int i = 0; i < 4; i++) {
            int idx = i * 256 + tid;
            int row = idx >> 3, c8 = idx & 7;
            int grow = rowBase + row;
            uint4 v = make_uint4(0, 0, 0, 0);
            if (grow < NN) {
                if (A1f) {
                    float4 f0 = *(const float4*)(A1f + (long)grow * 128 + k0 + c8 * 8);
                    float4 f1 = *(const float4*)(A1f + (long)grow * 128 + k0 + c8 * 8 + 4);
                    __half2 h0 = __floats2half2_rn(f0.x, f0.y);
                    __half2 h1 = __floats2half2_rn(f0.z, f0.w);
                    __half2 h2 = __floats2half2_rn(f1.x, f1.y);
                    __half2 h3 = __floats2half2_rn(f1.z, f1.w);
                    v = make_uint4(*(unsigned*)&h0, *(unsigned*)&h1,
                                   *(unsigned*)&h2, *(unsigned*)&h3);
                } else {
                    v = *(const uint4*)(A1 + (long)grow * 128 + k0 + c8 * 8);
                    if (hasB) {
                        uint4 u = *(const uint4*)(A2 + (long)grow * 128 + k0 + c8 * 8);
                        __half2* vh = (__half2*)&v;
                        __half2* uh = (__half2*)&u;
                        vh[0] = __hadd2(vh[0], uh[0]);
                        vh[1] = __hadd2(vh[1], uh[1]);
                        vh[2] = __hadd2(vh[2], uh[2]);
                        vh[3] = __hadd2(vh[3], uh[3]);
                    }
                }
            }
            *(uint4*)&sA[row * GP + c8 * 8] = v;
        }
#pragma unroll
        for (int i = 0; i < 4; i++) {
            int idx = i * 256 + tid;
            int row = idx >> 4, c8 = idx & 15;
            uint4 w = *(const uint4*)(Wh + (long)(k0 + row) * 128 + c8 * 8);
            *(uint4*)&sB[row * BP + c8 * 8] = w;
        }
        __syncthreads();

#pragma unroll
        for (int kk = 0; kk < 4; kk++) {
            unsigned a[2][4];
#pragma unroll
            for (int mi = 0; mi < 2; mi++) {
                unsigned addr = cvta_sh(&sA[(warpM * 32 + mi * 16 + (lane & 15)) * GP
                                            + kk * 16 + (lane >> 4) * 8]);
                ldm_x4(a[mi], addr);
            }
            unsigned b[4][4];
#pragma unroll
            for (int nj = 0; nj < 4; nj++) {
                unsigned addr = cvta_sh(&sB[(kk * 16 + (lane & 15)) * BP
                                            + warpN * 64 + nj * 16 + (lane >> 4) * 8]);
                ldm_x4_t(b[nj], addr);
            }
#pragma unroll
            for (int mi = 0; mi < 2; mi++)
#pragma unroll
                for (int ni = 0; ni < 8; ni++) {
                    unsigned b0 = b[ni >> 1][(ni & 1) * 2];
                    unsigned b1 = b[ni >> 1][(ni & 1) * 2 + 1];
                    mma16816(c[mi][ni], a[mi], b0, b1);
                }
        }
        __syncthreads();
    }

    int gID = lane >> 2, tig = lane & 3;
#pragma unroll
    for (int mi = 0; mi < 2; mi++) {
        int r0 = rowBase + warpM * 32 + mi * 16 + gID;
        int r1 = r0 + 8;
        float d0 = (r0 < NN && scaleOut) ? g_dinv[r0] : 1.f;
        float d1 = (r1 < NN && scaleOut) ? g_dinv[r1] : 1.f;
#pragma unroll
        for (int ni = 0; ni < 8; ni++) {
            int col = warpN * 64 + ni * 8 + tig * 2;
            if (r0 < NN) {
                __half2 h = __floats2half2_rn(d0 * c[mi][ni][0], d0 * c[mi][ni][1]);
                *(unsigned*)(Ch + (long)r0 * 128 + col) = *(unsigned*)&h;
            }
            if (r1 < NN) {
                __half2 h = __floats2half2_rn(d1 * c[mi][ni][2], d1 * c[mi][ni][3]);
                *(unsigned*)(Ch + (long)r1 * 128 + col) = *(unsigned*)&h;
            }
        }
    }
}

// ---------------- aggregation ----------------
__device__ __forceinline__ void fma_h4(float* acc, float w, uint4 v) {
    __half2* h = (__half2*)&v;
#pragma unroll
    for (int j = 0; j < 4; j++) {
        float2 f = __half22float2(h[j]);
        acc[2 * j]     = fmaf(w, f.x, acc[2 * j]);
        acc[2 * j + 1] = fmaf(w, f.y, acc[2 * j + 1]);
    }
}

// SCALESRC=1: tmp is unscaled; multiply each gathered row by dinv[src].
template <int SCALESRC>
__global__ __launch_bounds__(256) void agg_kernel(
    const uint4* __restrict__ tmp, const float* __restrict__ bias,
    uint4* __restrict__ out) {
    int lane16 = threadIdx.x & 15;
    int node = (blockIdx.x * blockDim.x + threadIdx.x) >> 4;
    if (node >= NN) return;

    int beg = g_rowptr[node];
    int end = g_rowptr[node + 1];

    float acc[8] = {0.f, 0.f, 0.f, 0.f, 0.f, 0.f, 0.f, 0.f};
    int e = beg;
    for (; e + 8 <= end; e += 8) {
        int s0 = g_col[e],     s1 = g_col[e + 1];
        int s2 = g_col[e + 2], s3 = g_col[e + 3];
        int s4 = g_col[e + 4], s5 = g_col[e + 5];
        int s6 = g_col[e + 6], s7 = g_col[e + 7];
        uint4 v0 = tmp[(long)s0 * 16 + lane16];
        uint4 v1 = tmp[(long)s1 * 16 + lane16];
        uint4 v2 = tmp[(long)s2 * 16 + lane16];
        uint4 v3 = tmp[(long)s3 * 16 + lane16];
        uint4 v4 = tmp[(long)s4 * 16 + lane16];
        uint4 v5 = tmp[(long)s5 * 16 + lane16];
        uint4 v6 = tmp[(long)s6 * 16 + lane16];
        uint4 v7 = tmp[(long)s7 * 16 + lane16];
        float w0 = SCALESRC ? g_dinv[s0] : 1.f;
        float w1 = SCALESRC ? g_dinv[s1] : 1.f;
        float w2 = SCALESRC ? g_dinv[s2] : 1.f;
        float w3 = SCALESRC ? g_dinv[s3] : 1.f;
        float w4 = SCALESRC ? g_dinv[s4] : 1.f;
        float w5 = SCALESRC ? g_dinv[s5] : 1.f;
        float w6 = SCALESRC ? g_dinv[s6] : 1.f;
        float w7 = SCALESRC ? g_dinv[s7] : 1.f;
        fma_h4(acc, w0, v0); fma_h4(acc, w1, v1);
        fma_h4(acc, w2, v2); fma_h4(acc, w3, v3);
        fma_h4(acc, w4, v4); fma_h4(acc, w5, v5);
        fma_h4(acc, w6, v6); fma_h4(acc, w7, v7);
    }
    for (; e < end; e++) {
        int s0 = g_col[e];
        uint4 v0 = tmp[(long)s0 * 16 + lane16];
        fma_h4(acc, SCALESRC ? g_dinv[s0] : 1.f, v0);
    }
    float di = g_dinv[node];
    uint4 vs = tmp[(long)node * 16 + lane16];
    fma_h4(acc, SCALESRC ? di : 1.f, vs);   // self loop

    float4 b0 = ((const float4*)bias)[lane16 * 2];
    float4 b1 = ((const float4*)bias)[lane16 * 2 + 1];
    float o[8];
    o[0] = fmaxf(fmaf(di, acc[0], b0.x), 0.f);
    o[1] = fmaxf(fmaf(di, acc[1], b0.y), 0.f);
    o[2] = fmaxf(fmaf(di, acc[2], b0.z), 0.f);
    o[3] = fmaxf(fmaf(di, acc[3], b0.w), 0.f);
    o[4] = fmaxf(fmaf(di, acc[4], b1.x), 0.f);
    o[5] = fmaxf(fmaf(di, acc[5], b1.y), 0.f);
    o[6] = fmaxf(fmaf(di, acc[6], b1.z), 0.f);
    o[7] = fmaxf(fmaf(di, acc[7], b1.w), 0.f);
    __half2 h[4];
    h[0] = __floats2half2_rn(o[0], o[1]);
    h[1] = __floats2half2_rn(o[2], o[3]);
    h[2] = __floats2half2_rn(o[4], o[5]);
    h[3] = __floats2half2_rn(o[6], o[7]);
    out[(long)node * 16 + lane16] = *(uint4*)h;
}

// ---------------- pooling over sorted batch ids ----------------
#define POOL_NODES 64
__global__ void pool_kernel(const __half* __restrict__ cur,
                            const void* __restrict__ batch) {
    int is64 = g_b64;
    int f = threadIdx.x;
    int start = blockIdx.x * POOL_NODES;
    if (start >= NN) return;
    int endn = start + POOL_NODES;
    if (endn > NN) endn = NN;

    int curg = load_idx(batch, start, is64);
    float acc = 0.f;
    int cnt = 0;
    for (int nd = start; nd < endn; nd++) {
        int gg = load_idx(batch, nd, is64);
        if (gg != curg) {
            atomicAdd(&g_gsum[curg * HID + f], acc);
            if (f == 0) atomicAdd(&g_gcnt[curg], cnt);
            acc = 0.f; cnt = 0; curg = gg;
        }
        acc += __half2float(cur[(long)nd * HID + f]);
        cnt++;
    }
    atomicAdd(&g_gsum[curg * HID + f], acc);
    if (f == 0) atomicAdd(&g_gcnt[curg], cnt);
}

// ---------------- mean + linear head + outputs ----------------
__global__ void final_kernel(const float* __restrict__ Wl,
                             const float* __restrict__ bl,
                             float* __restrict__ out) {
    __shared__ float sm[HID];
    int g = blockIdx.x;
    int f = threadIdx.x;
    float c = (float)g_gcnt[g];
    c = fmaxf(c, 1.f);
    float m = g_gsum[g * HID + f] / c;
    sm[f] = m;
    out[NGRAPH * NCLS + (long)g * HID + f] = m;
    __syncthreads();
    if (f < NCLS) {
        float y = bl[f];
#pragma unroll 8
        for (int k = 0; k < HID; k++) y = fmaf(sm[k], Wl[k * NCLS + f], y);
        out[g * NCLS + f] = y;
    }
}

// ---------------- host ----------------
extern "C" void kernel_launch(void* const* d_in, const int* in_sizes, int n_in,
                              void* d_out, int out_size) {
    const float* x     = (const float*)d_in[0];
    const void*  ei    = d_in[1];
    const void*  batch = d_in[2];
    const float* W_in  = (const float*)d_in[3];
    const float* b_in  = (const float*)d_in[4];
    const float* W_hid = (const float*)d_in[5];
    const float* b_hid = (const float*)d_in[6];
    const float* W_lin = (const float*)d_in[7];
    const float* b_lin = (const float*)d_in[8];
    float* out = (float*)d_out;

    __half *tmph, *hb0, *hb1, *hb2, *wh;
    cudaGetSymbolAddress((void**)&tmph, g_tmph);
    cudaGetSymbolAddress((void**)&hb0, g_hb0);
    cudaGetSymbolAddress((void**)&hb1, g_hb1);
    cudaGetSymbolAddress((void**)&hb2, g_hb2);
    cudaGetSymbolAddress((void**)&wh,  g_wh);

    const int GEMM_GRID = (NN + 127) / 128;
    const int AGG_GRID  = (NN * 16 + 255) / 256;

    cudaStream_t s2;
    cudaStreamCreate(&s2);
    cudaEvent_t evFork, evJoin;
    cudaEventCreateWithFlags(&evFork, cudaEventDisableTiming);
    cudaEventCreateWithFlags(&evJoin, cudaEventDisableTiming);

    // fork: s2 runs cvtW + input GEMM (unscaled) while main builds CSR
    cudaEventRecord(evFork, 0);
    cudaStreamWaitEvent(s2, evFork, 0);
    cvtW_kernel<<<(5 * 4096 + 255) / 256, 256, 0, s2>>>(
        (const float4*)W_in, (const float4*)W_hid);
    gemm_kernel<<<GEMM_GRID, 256, 0, s2>>>(nullptr, nullptr, 0, x, 0,
                                           wh + 0 * 16384, tmph);
    cudaEventRecord(evJoin, s2);

    // main stream: CSR build
    zero_kernel<<<(NGRAPH * HID + 255) / 256, 256>>>((const int*)ei,
                                                     (const int*)batch);
    hist_kernel<<<1024, 256>>>(ei);
    scan1_kernel<<<SCAN_NB, SCAN_TPB>>>();
    scan23_kernel<<<SCAN_NB, SCAN_TPB>>>();
    fill_kernel<<<1024, 256>>>(ei);

    // join: agg0 needs CSR + dinv + tmph
    cudaStreamWaitEvent(0, evJoin, 0);

    // layer chain
    agg_kernel<1><<<AGG_GRID, 256>>>((const uint4*)tmph, b_in, (uint4*)hb0);
    gemm_kernel<<<GEMM_GRID, 256>>>(hb0, hb0, 0, nullptr, 1, wh + 1 * 16384, tmph);
    agg_kernel<0><<<AGG_GRID, 256>>>((const uint4*)tmph, b_hid + 0 * HID, (uint4*)hb1);
    gemm_kernel<<<GEMM_GRID, 256>>>(hb1, hb0, 1, nullptr, 1, wh + 2 * 16384, tmph);
    agg_kernel<0><<<AGG_GRID, 256>>>((const uint4*)tmph, b_hid + 1 * HID, (uint4*)hb2);
    gemm_kernel<<<GEMM_GRID, 256>>>(hb2, hb1, 1, nullptr, 1, wh + 3 * 16384, tmph);
    agg_kernel<0><<<AGG_GRID, 256>>>((const uint4*)tmph, b_hid + 2 * HID, (uint4*)hb0);
    gemm_kernel<<<GEMM_GRID, 256>>>(hb0, hb2, 1, nullptr, 1, wh + 4 * 16384, tmph);
    agg_kernel<0><<<AGG_GRID, 256>>>((const uint4*)tmph, b_hid + 3 * HID, (uint4*)hb1);

    pool_kernel<<<(NN + POOL_NODES - 1) / POOL_NODES, 128>>>(hb1, batch);
    final_kernel<<<NGRAPH, HID>>>(W_lin, b_lin, out);

    cudaEventDestroy(evFork);
    cudaEventDestroy(evJoin);
    cudaStreamDestroy(s2);
}

// round 13
// speedup vs baseline: 1.1508x; 1.0466x over previous
#include <cuda_runtime.h>
#include <cuda_fp16.h>

#define NN 50000
#define EE 800000
#define HID 128
#define NCLS 16
#define NGRAPH 512

#define SCAN_TPB 256
#define SCAN_NB ((NN + SCAN_TPB - 1) / SCAN_TPB)   // 196

// ---------------- device scratch (no allocation allowed) ----------------
__device__ __half g_tmph[NN * HID];
__device__ __half g_hb0 [NN * HID];
__device__ __half g_hb1 [NN * HID];
__device__ __half g_hb2 [NN * HID];
__device__ __half g_wh  [5 * HID * HID];

__device__ int   g_cnt[NN];
__device__ int   g_rowptr[NN + 1];
__device__ int   g_cursor[NN];
__device__ int   g_col[EE];
__device__ float g_dinv[NN];
__device__ int   g_bsum[SCAN_NB];

__device__ float g_gsum[NGRAPH * HID];
__device__ int   g_gcnt[NGRAPH];

__device__ int   g_ei64;
__device__ int   g_b64;

__device__ __forceinline__ int load_idx(const void* p, long i, int is64) {
    return is64 ? (int)((const long long*)p)[i] : ((const int*)p)[i];
}

// ---------------- zero + dtype detection (merged) ----------------
__global__ void zero_kernel(const int* __restrict__ ei,
                            const int* __restrict__ batch) {
    int i = blockIdx.x * blockDim.x + threadIdx.x;
    if (i < NGRAPH * HID) g_gsum[i] = 0.f;
    if (i < NGRAPH) g_gcnt[i] = 0;
    if (i < NN) g_cnt[i] = 0;
    if (blockIdx.x == 0 && threadIdx.x == 0) {
        int z = 1;
        for (int k = 1; k < 257; k += 2) if (ei[k] != 0) { z = 0; break; }
        g_ei64 = z;
        z = 1;
        for (int k = 25001; k < 25257; k += 2) if (batch[k] != 0) { z = 0; break; }
        g_b64 = z;
    }
}

// ---------------- weight pre-conversion (fp32 -> fp16, once) --------------
__global__ void cvtW_kernel(const float4* __restrict__ Win,
                            const float4* __restrict__ Whid) {
    int i = blockIdx.x * blockDim.x + threadIdx.x;
    if (i >= 5 * 4096) return;
    float4 v = (i < 4096) ? Win[i] : Whid[i - 4096];
    __half2 h0 = __floats2half2_rn(v.x, v.y);
    __half2 h1 = __floats2half2_rn(v.z, v.w);
    ((uint2*)g_wh)[i] = make_uint2(*(unsigned*)&h0, *(unsigned*)&h1);
}

// ---------------- CSR build ----------------
__global__ void hist_kernel(const void* __restrict__ ei) {
    int is64 = g_ei64;
    int tid2 = blockIdx.x * blockDim.x + threadIdx.x;
    if (is64) {
        const longlong2* dst2 = (const longlong2*)((const long long*)ei + EE);
        for (int p = tid2; p < EE / 2; p += gridDim.x * blockDim.x) {
            longlong2 d = dst2[p];
            atomicAdd(&g_cnt[(int)d.x], 1);
            atomicAdd(&g_cnt[(int)d.y], 1);
        }
    } else {
        const int2* dst2 = (const int2*)((const int*)ei + EE);
        for (int p = tid2; p < EE / 2; p += gridDim.x * blockDim.x) {
            int2 d = dst2[p];
            atomicAdd(&g_cnt[d.x], 1);
            atomicAdd(&g_cnt[d.y], 1);
        }
    }
}

__global__ __launch_bounds__(SCAN_TPB) void scan1_kernel() {
    __shared__ int sh[SCAN_TPB];
    int tid = threadIdx.x;
    int i = blockIdx.x * SCAN_TPB + tid;
    int c = (i < NN) ? g_cnt[i] : 0;
    if (i < NN) g_dinv[i] = rsqrtf((float)(c + 1));
    sh[tid] = c;
    __syncthreads();
#pragma unroll
    for (int off = 1; off < SCAN_TPB; off <<= 1) {
        int v = (tid >= off) ? sh[tid - off] : 0;
        __syncthreads();
        sh[tid] += v;
        __syncthreads();
    }
    if (i < NN) g_rowptr[i] = sh[tid] - c;
    if (tid == SCAN_TPB - 1) g_bsum[blockIdx.x] = sh[tid];
}

// merged scan2+scan3
__global__ __launch_bounds__(SCAN_TPB) void scan23_kernel() {
    __shared__ int sh[SCAN_TPB];
    int tid = threadIdx.x;
    sh[tid] = (tid < (int)blockIdx.x && tid < SCAN_NB) ? g_bsum[tid] : 0;
    __syncthreads();
#pragma unroll
    for (int off = SCAN_TPB / 2; off > 0; off >>= 1) {
        if (tid < off) sh[tid] += sh[tid + off];
        __syncthreads();
    }
    int offset = sh[0];
    int i = blockIdx.x * SCAN_TPB + tid;
    if (i < NN) {
        int v = g_rowptr[i] + offset;
        g_rowptr[i] = v;
        g_cursor[i] = v;
    }
    if (i == 0) g_rowptr[NN] = EE;
}

__global__ void fill_kernel(const void* __restrict__ ei) {
    int is64 = g_ei64;
    int tid2 = blockIdx.x * blockDim.x + threadIdx.x;
    if (is64) {
        const longlong2* src2 = (const longlong2*)ei;
        const longlong2* dst2 = (const longlong2*)((const long long*)ei + EE);
        for (int p = tid2; p < EE / 2; p += gridDim.x * blockDim.x) {
            longlong2 s = src2[p];
            longlong2 d = dst2[p];
            int pos0 = atomicAdd(&g_cursor[(int)d.x], 1);
            g_col[pos0] = (int)s.x;
            int pos1 = atomicAdd(&g_cursor[(int)d.y], 1);
            g_col[pos1] = (int)s.y;
        }
    } else {
        const int2* src2 = (const int2*)ei;
        const int2* dst2 = (const int2*)((const int*)ei + EE);
        for (int p = tid2; p < EE / 2; p += gridDim.x * blockDim.x) {
            int2 s = src2[p];
            int2 d = dst2[p];
            int pos0 = atomicAdd(&g_cursor[d.x], 1);
            g_col[pos0] = s.x;
            int pos1 = atomicAdd(&g_cursor[d.y], 1);
            g_col[pos1] = s.y;
        }
    }
}

// ---------------- tensor-core GEMM ----------------
#define GP 72    // sA pitch (halves)
#define BP 136   // sB pitch (halves)

__device__ __forceinline__ unsigned cvta_sh(const void* p) {
    return (unsigned)__cvta_generic_to_shared(p);
}
__device__ __forceinline__ void ldm_x4(unsigned* r, unsigned addr) {
    asm volatile("ldmatrix.sync.aligned.m8n8.x4.shared.b16 {%0,%1,%2,%3}, [%4];"
                 : "=r"(r[0]), "=r"(r[1]), "=r"(r[2]), "=r"(r[3]) : "r"(addr));
}
__device__ __forceinline__ void ldm_x4_t(unsigned* r, unsigned addr) {
    asm volatile("ldmatrix.sync.aligned.m8n8.x4.trans.shared.b16 {%0,%1,%2,%3}, [%4];"
                 : "=r"(r[0]), "=r"(r[1]), "=r"(r[2]), "=r"(r[3]) : "r"(addr));
}
__device__ __forceinline__ void mma16816(float* c, const unsigned* a,
                                         unsigned b0, unsigned b1) {
    asm volatile(
        "mma.sync.aligned.m16n8k16.row.col.f32.f16.f16.f32 "
        "{%0,%1,%2,%3}, {%4,%5,%6,%7}, {%8,%9}, {%0,%1,%2,%3};"
        : "+f"(c[0]), "+f"(c[1]), "+f"(c[2]), "+f"(c[3])
        : "r"(a[0]), "r"(a[1]), "r"(a[2]), "r"(a[3]), "r"(b0), "r"(b1));
}

// A1f != null: fp32 rows from A1f; scaleOut: multiply rows by dinv[row].
__global__ __launch_bounds__(256, 2) void gemm_kernel(
    const __half* __restrict__ A1, const __half* __restrict__ A2, int hasB,
    const float* __restrict__ A1f, int scaleOut,
    const __half* __restrict__ Wh, __half* __restrict__ Ch) {
    __shared__ __half sA[128 * GP];
    __shared__ __half sB[64 * BP];

    int tid = threadIdx.x;
    int lane = tid & 31, wid = tid >> 5;
    int warpM = wid & 3, warpN = wid >> 2;
    int rowBase = blockIdx.x * 128;

    float c[2][8][4];
#pragma unroll
    for (int mi = 0; mi < 2; mi++)
#pragma unroll
        for (int ni = 0; ni < 8; ni++)
#pragma unroll
            for (int j = 0; j < 4; j++) c[mi][ni][j] = 0.f;

    for (int k0 = 0; k0 < 128; k0 += 64) {
#pragma unroll
        for (int i = 0; i < 4; i++) {
            int idx = i * 256 + tid;
            int row = idx >> 3, c8 = idx & 7;
            int grow = rowBase + row;
            uint4 v = make_uint4(0, 0, 0, 0);
            if (grow < NN) {
                if (A1f) {
                    float4 f0 = *(const float4*)(A1f + (long)grow * 128 + k0 + c8 * 8);
                    float4 f1 = *(const float4*)(A1f + (long)grow * 128 + k0 + c8 * 8 + 4);
                    __half2 h0 = __floats2half2_rn(f0.x, f0.y);
                    __half2 h1 = __floats2half2_rn(f0.z, f0.w);
                    __half2 h2 = __floats2half2_rn(f1.x, f1.y);
                    __half2 h3 = __floats2half2_rn(f1.z, f1.w);
                    v = make_uint4(*(unsigned*)&h0, *(unsigned*)&h1,
                                   *(unsigned*)&h2, *(unsigned*)&h3);
                } else {
                    v = *(const uint4*)(A1 + (long)grow * 128 + k0 + c8 * 8);
                    if (hasB) {
                        uint4 u = *(const uint4*)(A2 + (long)grow * 128 + k0 + c8 * 8);
                        __half2* vh = (__half2*)&v;
                        __half2* uh = (__half2*)&u;
                        vh[0] = __hadd2(vh[0], uh[0]);
                        vh[1] = __hadd2(vh[1], uh[1]);
                        vh[2] = __hadd2(vh[2], uh[2]);
                        vh[3] = __hadd2(vh[3], uh[3]);
                    }
                }
            }
            *(uint4*)&sA[row * GP + c8 * 8] = v;
        }
#pragma unroll
        for (int i = 0; i < 4; i++) {
            int idx = i * 256 + tid;
            int row = idx >> 4, c8 = idx & 15;
            uint4 w = *(const uint4*)(Wh + (long)(k0 + row) * 128 + c8 * 8);
            *(uint4*)&sB[row * BP + c8 * 8] = w;
        }
        __syncthreads();

#pragma unroll
        for (int kk = 0; kk < 4; kk++) {
            unsigned a[2][4];
#pragma unroll
            for (int mi = 0; mi < 2; mi++) {
                unsigned addr = cvta_sh(&sA[(warpM * 32 + mi * 16 + (lane & 15)) * GP
                                            + kk * 16 + (lane >> 4) * 8]);
                ldm_x4(a[mi], addr);
            }
            unsigned b[4][4];
#pragma unroll
            for (int nj = 0; nj < 4; nj++) {
                unsigned addr = cvta_sh(&sB[(kk * 16 + (lane & 15)) * BP
                                            + warpN * 64 + nj * 16 + (lane >> 4) * 8]);
                ldm_x4_t(b[nj], addr);
            }
#pragma unroll
            for (int mi = 0; mi < 2; mi++)
#pragma unroll
                for (int ni = 0; ni < 8; ni++) {
                    unsigned b0 = b[ni >> 1][(ni & 1) * 2];
                    unsigned b1 = b[ni >> 1][(ni & 1) * 2 + 1];
                    mma16816(c[mi][ni], a[mi], b0, b1);
                }
        }
        __syncthreads();
    }

    int gID = lane >> 2, tig = lane & 3;
#pragma unroll
    for (int mi = 0; mi < 2; mi++) {
        int r0 = rowBase + warpM * 32 + mi * 16 + gID;
        int r1 = r0 + 8;
        float d0 = (r0 < NN && scaleOut) ? g_dinv[r0] : 1.f;
        float d1 = (r1 < NN && scaleOut) ? g_dinv[r1] : 1.f;
#pragma unroll
        for (int ni = 0; ni < 8; ni++) {
            int col = warpN * 64 + ni * 8 + tig * 2;
            if (r0 < NN) {
                __half2 h = __floats2half2_rn(d0 * c[mi][ni][0], d0 * c[mi][ni][1]);
                *(unsigned*)(Ch + (long)r0 * 128 + col) = *(unsigned*)&h;
            }
            if (r1 < NN) {
                __half2 h = __floats2half2_rn(d1 * c[mi][ni][2], d1 * c[mi][ni][3]);
                *(unsigned*)(Ch + (long)r1 * 128 + col) = *(unsigned*)&h;
            }
        }
    }
}

// ---------------- aggregation ----------------
__device__ __forceinline__ void fma_h4(float* acc, float w, uint4 v) {
    __half2* h = (__half2*)&v;
#pragma unroll
    for (int j = 0; j < 4; j++) {
        float2 f = __half22float2(h[j]);
        acc[2 * j]     = fmaf(w, f.x, acc[2 * j]);
        acc[2 * j + 1] = fmaf(w, f.y, acc[2 * j + 1]);
    }
}

// computes o[8] = relu(dinv[node]*sum + bias) for one node, lane16's features
__device__ __forceinline__ void agg_node(int node, int lane16, int scalesrc,
                                         const uint4* __restrict__ tmp,
                                         const float* __restrict__ bias,
                                         float* o) {
    int beg = g_rowptr[node];
    int end = g_rowptr[node + 1];
    float acc[8] = {0.f, 0.f, 0.f, 0.f, 0.f, 0.f, 0.f, 0.f};
    int e = beg;
    for (; e + 8 <= end; e += 8) {
        int s0 = g_col[e],     s1 = g_col[e + 1];
        int s2 = g_col[e + 2], s3 = g_col[e + 3];
        int s4 = g_col[e + 4], s5 = g_col[e + 5];
        int s6 = g_col[e + 6], s7 = g_col[e + 7];
        uint4 v0 = tmp[(long)s0 * 16 + lane16];
        uint4 v1 = tmp[(long)s1 * 16 + lane16];
        uint4 v2 = tmp[(long)s2 * 16 + lane16];
        uint4 v3 = tmp[(long)s3 * 16 + lane16];
        uint4 v4 = tmp[(long)s4 * 16 + lane16];
        uint4 v5 = tmp[(long)s5 * 16 + lane16];
        uint4 v6 = tmp[(long)s6 * 16 + lane16];
        uint4 v7 = tmp[(long)s7 * 16 + lane16];
        float w0 = scalesrc ? g_dinv[s0] : 1.f;
        float w1 = scalesrc ? g_dinv[s1] : 1.f;
        float w2 = scalesrc ? g_dinv[s2] : 1.f;
        float w3 = scalesrc ? g_dinv[s3] : 1.f;
        float w4 = scalesrc ? g_dinv[s4] : 1.f;
        float w5 = scalesrc ? g_dinv[s5] : 1.f;
        float w6 = scalesrc ? g_dinv[s6] : 1.f;
        float w7 = scalesrc ? g_dinv[s7] : 1.f;
        fma_h4(acc, w0, v0); fma_h4(acc, w1, v1);
        fma_h4(acc, w2, v2); fma_h4(acc, w3, v3);
        fma_h4(acc, w4, v4); fma_h4(acc, w5, v5);
        fma_h4(acc, w6, v6); fma_h4(acc, w7, v7);
    }
    for (; e < end; e++) {
        int s0 = g_col[e];
        uint4 v0 = tmp[(long)s0 * 16 + lane16];
        fma_h4(acc, scalesrc ? g_dinv[s0] : 1.f, v0);
    }
    float di = g_dinv[node];
    uint4 vs = tmp[(long)node * 16 + lane16];
    fma_h4(acc, scalesrc ? di : 1.f, vs);   // self loop

    float4 b0 = ((const float4*)bias)[lane16 * 2];
    float4 b1 = ((const float4*)bias)[lane16 * 2 + 1];
    o[0] = fmaxf(fmaf(di, acc[0], b0.x), 0.f);
    o[1] = fmaxf(fmaf(di, acc[1], b0.y), 0.f);
    o[2] = fmaxf(fmaf(di, acc[2], b0.z), 0.f);
    o[3] = fmaxf(fmaf(di, acc[3], b0.w), 0.f);
    o[4] = fmaxf(fmaf(di, acc[4], b1.x), 0.f);
    o[5] = fmaxf(fmaf(di, acc[5], b1.y), 0.f);
    o[6] = fmaxf(fmaf(di, acc[6], b1.z), 0.f);
    o[7] = fmaxf(fmaf(di, acc[7], b1.w), 0.f);
}

template <int SCALESRC>
__global__ __launch_bounds__(256) void agg_kernel(
    const uint4* __restrict__ tmp, const float* __restrict__ bias,
    uint4* __restrict__ out) {
    int lane16 = threadIdx.x & 15;
    int node = (blockIdx.x * blockDim.x + threadIdx.x) >> 4;
    if (node >= NN) return;
    float o[8];
    agg_node(node, lane16, SCALESRC, tmp, bias, o);
    __half2 h[4];
    h[0] = __floats2half2_rn(o[0], o[1]);
    h[1] = __floats2half2_rn(o[2], o[3]);
    h[2] = __floats2half2_rn(o[4], o[5]);
    h[3] = __floats2half2_rn(o[6], o[7]);
    out[(long)node * 16 + lane16] = *(uint4*)h;
}

// ---------------- fused final aggregation + mean-pool accumulation --------
// 16 consecutive nodes per block (sorted batch => <=2 graph segments typical)
__global__ __launch_bounds__(256) void agg_pool_kernel(
    const uint4* __restrict__ tmp, const float* __restrict__ bias,
    const void* __restrict__ batch) {
    __shared__ float sacc[16][HID];
    __shared__ int sgid[16];
    __shared__ int sboundary, smulti;

    int tid = threadIdx.x;
    int lane16 = tid & 15;
    int hw = tid >> 4;                 // 0..15
    int node = blockIdx.x * 16 + hw;   // NN = 50000 = 3125*16, always in range

    float o[8];
    agg_node(node, lane16, 0, tmp, bias, o);

    int gid = load_idx(batch, node, g_b64);
    if (lane16 == 0) sgid[hw] = gid;
#pragma unroll
    for (int j = 0; j < 8; j++) sacc[hw][lane16 * 8 + j] = o[j];
    __syncthreads();

    if (tid == 0) {
        int b = 16, t = 0;
        for (int i = 1; i < 16; i++)
            if (sgid[i] != sgid[i - 1]) { t++; b = i; }
        sboundary = b;
        smulti = (t > 1);
    }
    __syncthreads();

    if (!smulti) {
        int b = sboundary;
        if (tid < HID) {
            float a = 0.f;
            for (int h = 0; h < b; h++) a += sacc[h][tid];
            atomicAdd(&g_gsum[sgid[0] * HID + tid], a);
        } else if (b < 16) {
            int f = tid - HID;
            float a = 0.f;
            for (int h = b; h < 16; h++) a += sacc[h][f];
            atomicAdd(&g_gsum[sgid[b] * HID + f], a);
        }
        if (tid == 0) atomicAdd(&g_gcnt[sgid[0]], b);
        if (tid == HID && sboundary < 16)
            atomicAdd(&g_gcnt[sgid[sboundary]], 16 - sboundary);
    } else {
        // rare: >2 segments in one block — per-node atomics
#pragma unroll
        for (int j = 0; j < 8; j++)
            atomicAdd(&g_gsum[gid * HID + lane16 * 8 + j], o[j]);
        if (lane16 == 0) atomicAdd(&g_gcnt[gid], 1);
    }
}

// ---------------- mean + linear head + outputs ----------------
__global__ void final_kernel(const float* __restrict__ Wl,
                             const float* __restrict__ bl,
                             float* __restrict__ out) {
    __shared__ float sm[HID];
    int g = blockIdx.x;
    int f = threadIdx.x;
    float c = (float)g_gcnt[g];
    c = fmaxf(c, 1.f);
    float m = g_gsum[g * HID + f] / c;
    sm[f] = m;
    out[NGRAPH * NCLS + (long)g * HID + f] = m;
    __syncthreads();
    if (f < NCLS) {
        float y = bl[f];
#pragma unroll 8
        for (int k = 0; k < HID; k++) y = fmaf(sm[k], Wl[k * NCLS + f], y);
        out[g * NCLS + f] = y;
    }
}

// ---------------- host ----------------
extern "C" void kernel_launch(void* const* d_in, const int* in_sizes, int n_in,
                              void* d_out, int out_size) {
    const float* x     = (const float*)d_in[0];
    const void*  ei    = d_in[1];
    const void*  batch = d_in[2];
    const float* W_in  = (const float*)d_in[3];
    const float* b_in  = (const float*)d_in[4];
    const float* W_hid = (const float*)d_in[5];
    const float* b_hid = (const float*)d_in[6];
    const float* W_lin = (const float*)d_in[7];
    const float* b_lin = (const float*)d_in[8];
    float* out = (float*)d_out;

    __half *tmph, *hb0, *hb1, *hb2, *wh;
    cudaGetSymbolAddress((void**)&tmph, g_tmph);
    cudaGetSymbolAddress((void**)&hb0, g_hb0);
    cudaGetSymbolAddress((void**)&hb1, g_hb1);
    cudaGetSymbolAddress((void**)&hb2, g_hb2);
    cudaGetSymbolAddress((void**)&wh,  g_wh);

    const int GEMM_GRID = (NN + 127) / 128;
    const int AGG_GRID  = (NN * 16 + 255) / 256;

    cudaStream_t s2;
    cudaStreamCreate(&s2);
    cudaEvent_t evFork, evJoin;
    cudaEventCreateWithFlags(&evFork, cudaEventDisableTiming);
    cudaEventCreateWithFlags(&evJoin, cudaEventDisableTiming);

    // fork: s2 runs cvtW + input GEMM (unscaled) while main builds CSR
    cudaEventRecord(evFork, 0);
    cudaStreamWaitEvent(s2, evFork, 0);
    cvtW_kernel<<<(5 * 4096 + 255) / 256, 256, 0, s2>>>(
        (const float4*)W_in, (const float4*)W_hid);
    gemm_kernel<<<GEMM_GRID, 256, 0, s2>>>(nullptr, nullptr, 0, x, 0,
                                           wh + 0 * 16384, tmph);
    cudaEventRecord(evJoin, s2);

    // main stream: CSR build
    zero_kernel<<<(NGRAPH * HID + 255) / 256, 256>>>((const int*)ei,
                                                     (const int*)batch);
    hist_kernel<<<1024, 256>>>(ei);
    scan1_kernel<<<SCAN_NB, SCAN_TPB>>>();
    scan23_kernel<<<SCAN_NB, SCAN_TPB>>>();
    fill_kernel<<<1024, 256>>>(ei);

    // join: agg0 needs CSR + dinv + tmph
    cudaStreamWaitEvent(0, evJoin, 0);

    // layer chain
    agg_kernel<1><<<AGG_GRID, 256>>>((const uint4*)tmph, b_in, (uint4*)hb0);
    gemm_kernel<<<GEMM_GRID, 256>>>(hb0, hb0, 0, nullptr, 1, wh + 1 * 16384, tmph);
    agg_kernel<0><<<AGG_GRID, 256>>>((const uint4*)tmph, b_hid + 0 * HID, (uint4*)hb1);
    gemm_kernel<<<GEMM_GRID, 256>>>(hb1, hb0, 1, nullptr, 1, wh + 2 * 16384, tmph);
    agg_kernel<0><<<AGG_GRID, 256>>>((const uint4*)tmph, b_hid + 1 * HID, (uint4*)hb2);
    gemm_kernel<<<GEMM_GRID, 256>>>(hb2, hb1, 1, nullptr, 1, wh + 3 * 16384, tmph);
    agg_kernel<0><<<AGG_GRID, 256>>>((const uint4*)tmph, b_hid + 2 * HID, (uint4*)hb0);
    gemm_kernel<<<GEMM_GRID, 256>>>(hb0, hb2, 1, nullptr, 1, wh + 4 * 16384, tmph);

    // fused final agg + pool (writes g_gsum/g_gcnt directly)
    agg_pool_kernel<<<NN / 16, 256>>>((const uint4*)tmph, b_hid + 3 * HID, batch);

    final_kernel<<<NGRAPH, HID>>>(W_lin, b_lin, out);

    cudaEventDestroy(evFork);
    cudaEventDestroy(evJoin);
    cudaStreamDestroy(s2);
}